// round 8
// baseline (speedup 1.0000x reference)
#include <cuda_runtime.h>

typedef unsigned long long u64;

// ---------------- packed f32x2 helpers (Blackwell FFMA2) ----------------
__device__ __forceinline__ u64 pack2(float a, float b) {
    u64 r; asm("mov.b64 %0, {%1, %2};" : "=l"(r) : "f"(a), "f"(b)); return r;
}
__device__ __forceinline__ u64 pack1(float a) { return pack2(a, a); }
__device__ __forceinline__ void unpack2(u64 v, float& a, float& b) {
    asm("mov.b64 {%0, %1}, %2;" : "=f"(a), "=f"(b) : "l"(v));
}
__device__ __forceinline__ u64 fma2(u64 a, u64 b, u64 c) {
    u64 d; asm("fma.rn.f32x2 %0, %1, %2, %3;" : "=l"(d) : "l"(a), "l"(b), "l"(c));
    return d;
}
__device__ __forceinline__ u64 relu2(u64 v) {
    float a, b; unpack2(v, a, b);
    a = fmaxf(a, 0.0f); b = fmaxf(b, 0.0f);
    return pack2(a, b);
}

// ---------------- constants ----------------
#define NTHREADS 256
#define ROWS_PER_THREAD 4
#define PAIRS 2
static constexpr int BATCH = 2097152;
static constexpr int CHUNK = BATCH / ROWS_PER_THREAD;  // 524288

// ---------------- shared weight table (u64 indices), raw, bias embedded --
// W0: 5 rows stride 10 [w0..w7, b, pad]    [0,50)
// W1..W4: 5 rows stride 6 [w0..w4, b]      [50,80) [80,110) [110,140) [140,170)
// W5: 4 rows stride 6 [w0..w4, b]          [170,194)
#define OFF_W0   0
#define OFF_W1   50
#define OFF_W2   80
#define OFF_W3   110
#define OFF_W4   140
#define OFF_W5   170
#define W_TOTAL  194

// raw table entry t: a single LDG from the right source (no arithmetic)
__device__ __forceinline__ float table_entry(
    int t,
    const float* __restrict__ W0, const float* __restrict__ b0,
    const float* __restrict__ W1, const float* __restrict__ b1,
    const float* __restrict__ W2, const float* __restrict__ b2,
    const float* __restrict__ W3, const float* __restrict__ b3,
    const float* __restrict__ W4, const float* __restrict__ b4,
    const float* __restrict__ W5, const float* __restrict__ b5) {
    if (t < 50) {
        int o = t / 10, k = t % 10;
        return (k < 8) ? W0[o * 8 + k] : ((k == 8) ? b0[o] : 0.0f);
    } else if (t < 80) {
        int i = t - OFF_W1, o = i / 6, k = i % 6;
        return (k < 5) ? W1[o * 5 + k] : b1[o];
    } else if (t < 110) {
        int i = t - OFF_W2, o = i / 6, k = i % 6;
        return (k < 5) ? W2[o * 5 + k] : b2[o];
    } else if (t < 140) {
        int i = t - OFF_W3, o = i / 6, k = i % 6;
        return (k < 5) ? W3[o * 5 + k] : b3[o];
    } else if (t < 170) {
        int i = t - OFF_W4, o = i / 6, k = i % 6;
        return (k < 5) ? W4[o * 5 + k] : b4[o];
    } else {
        int i = t - OFF_W5, o = i / 6, k = i % 6;
        return (k < 5) ? W5[o * 5 + k] : b5[o];
    }
}

// one hidden stage (5 -> relu(5)) applied to both pairs; 3 LDS.128 per row
__device__ __forceinline__ void hidden_stage(u64 a[PAIRS][5], const u64* sw, int woff) {
    u64 h[PAIRS][5];
#pragma unroll
    for (int o = 0; o < 5; o++) {
        ulonglong2 wa = *reinterpret_cast<const ulonglong2*>(sw + woff + o * 6);
        ulonglong2 wb = *reinterpret_cast<const ulonglong2*>(sw + woff + o * 6 + 2);
        ulonglong2 wc = *reinterpret_cast<const ulonglong2*>(sw + woff + o * 6 + 4);
#pragma unroll
        for (int p = 0; p < PAIRS; p++) {
            u64 acc = wc.y;  // bias
            acc = fma2(a[p][0], wa.x, acc);
            acc = fma2(a[p][1], wa.y, acc);
            acc = fma2(a[p][2], wb.x, acc);
            acc = fma2(a[p][3], wb.y, acc);
            acc = fma2(a[p][4], wc.x, acc);
            h[p][o] = relu2(acc);
        }
    }
#pragma unroll
    for (int p = 0; p < PAIRS; p++)
#pragma unroll
        for (int o = 0; o < 5; o++) a[p][o] = h[p][o];
}

// stage 0+1 for ONE pair: load 2 rows, layer0 (8->5, NO relu), layer1 (5->relu(5))
// keeps only ~16 input regs + 10 temp regs live
__device__ __forceinline__ void stage01_pair(u64 aout[5], const u64* sw,
                                             const float4* xr_a, const float4* xr_b) {
    float4 a0 = __ldg(xr_a), a1 = __ldg(xr_a + 1);
    float4 c0 = __ldg(xr_b), c1 = __ldg(xr_b + 1);
    u64 xv[8];
    xv[0] = pack2(a0.x, c0.x); xv[1] = pack2(a0.y, c0.y);
    xv[2] = pack2(a0.z, c0.z); xv[3] = pack2(a0.w, c0.w);
    xv[4] = pack2(a1.x, c1.x); xv[5] = pack2(a1.y, c1.y);
    xv[6] = pack2(a1.z, c1.z); xv[7] = pack2(a1.w, c1.w);

    // layer0: 8 -> 5, no relu
    u64 t0[5];
#pragma unroll
    for (int o = 0; o < 5; o++) {
        ulonglong2 wa = *reinterpret_cast<const ulonglong2*>(sw + OFF_W0 + o * 10);
        ulonglong2 wb = *reinterpret_cast<const ulonglong2*>(sw + OFF_W0 + o * 10 + 2);
        ulonglong2 wc = *reinterpret_cast<const ulonglong2*>(sw + OFF_W0 + o * 10 + 4);
        ulonglong2 wd = *reinterpret_cast<const ulonglong2*>(sw + OFF_W0 + o * 10 + 6);
        ulonglong2 we = *reinterpret_cast<const ulonglong2*>(sw + OFF_W0 + o * 10 + 8);
        u64 acc = we.x;  // bias
        acc = fma2(xv[0], wa.x, acc);
        acc = fma2(xv[1], wa.y, acc);
        acc = fma2(xv[2], wb.x, acc);
        acc = fma2(xv[3], wb.y, acc);
        acc = fma2(xv[4], wc.x, acc);
        acc = fma2(xv[5], wc.y, acc);
        acc = fma2(xv[6], wd.x, acc);
        acc = fma2(xv[7], wd.y, acc);
        t0[o] = acc;
    }

    // layer1: 5 -> relu(5)
#pragma unroll
    for (int o = 0; o < 5; o++) {
        ulonglong2 wa = *reinterpret_cast<const ulonglong2*>(sw + OFF_W1 + o * 6);
        ulonglong2 wb = *reinterpret_cast<const ulonglong2*>(sw + OFF_W1 + o * 6 + 2);
        ulonglong2 wc = *reinterpret_cast<const ulonglong2*>(sw + OFF_W1 + o * 6 + 4);
        u64 acc = wc.y;  // bias
        acc = fma2(t0[0], wa.x, acc);
        acc = fma2(t0[1], wa.y, acc);
        acc = fma2(t0[2], wb.x, acc);
        acc = fma2(t0[3], wb.y, acc);
        acc = fma2(t0[4], wc.x, acc);
        aout[o] = relu2(acc);
    }
}

__global__ __launch_bounds__(NTHREADS, 5) void mlp_kernel(
    const float4* __restrict__ x, float4* __restrict__ out,
    const float* __restrict__ W0, const float* __restrict__ b0,
    const float* __restrict__ W1, const float* __restrict__ b1,
    const float* __restrict__ W2, const float* __restrict__ b2,
    const float* __restrict__ W3, const float* __restrict__ b3,
    const float* __restrict__ W4, const float* __restrict__ b4,
    const float* __restrict__ W5, const float* __restrict__ b5) {
    __shared__ __align__(16) u64 sw[W_TOTAL];
    const int t = threadIdx.x;
    const int idx = blockIdx.x * NTHREADS + t;  // 0..CHUNK-1

    // raw weight table: one LDG + STS per thread (no fusion arithmetic)
    if (t < W_TOTAL)
        sw[t] = pack1(table_entry(t, W0, b0, W1, b1, W2, b2, W3, b3, W4, b4, W5, b5));
    __syncthreads();

    const float4* xp = x + 2u * (unsigned)idx;

    // ---- stages 0+1, per pair (keeps register peak low) ----
    u64 a[PAIRS][5];
    stage01_pair(a[0], sw, xp,                          xp + (size_t)(2 * CHUNK));
    stage01_pair(a[1], sw, xp + (size_t)(4 * CHUNK),    xp + (size_t)(6 * CHUNK));

    // ---- stages 2..4: hidden layers, pair-amortized weights ----
    hidden_stage(a, sw, OFF_W2);
    hidden_stage(a, sw, OFF_W3);
    hidden_stage(a, sw, OFF_W4);

    // ---- stage 5: output layer (5 -> relu(4)) + streaming store ----
    float res[ROWS_PER_THREAD][4];
#pragma unroll
    for (int o = 0; o < 4; o++) {
        ulonglong2 wa = *reinterpret_cast<const ulonglong2*>(sw + OFF_W5 + o * 6);
        ulonglong2 wb = *reinterpret_cast<const ulonglong2*>(sw + OFF_W5 + o * 6 + 2);
        ulonglong2 wc = *reinterpret_cast<const ulonglong2*>(sw + OFF_W5 + o * 6 + 4);
#pragma unroll
        for (int p = 0; p < PAIRS; p++) {
            u64 acc = wc.y;  // bias
            acc = fma2(a[p][0], wa.x, acc);
            acc = fma2(a[p][1], wa.y, acc);
            acc = fma2(a[p][2], wb.x, acc);
            acc = fma2(a[p][3], wb.y, acc);
            acc = fma2(a[p][4], wc.x, acc);
            acc = relu2(acc);
            unpack2(acc, res[2 * p][o], res[2 * p + 1][o]);
        }
    }
    float4* op = out + idx;
#pragma unroll
    for (int r = 0; r < ROWS_PER_THREAD; r++) {
        __stcs(op + (size_t)r * CHUNK,
               make_float4(res[r][0], res[r][1], res[r][2], res[r][3]));
    }
}

extern "C" void kernel_launch(void* const* d_in, const int* in_sizes, int n_in,
                              void* d_out, int out_size) {
    const float* x  = (const float*)d_in[0];
    const float* W0 = (const float*)d_in[1];
    const float* b0 = (const float*)d_in[2];
    const float* W1 = (const float*)d_in[3];
    const float* b1 = (const float*)d_in[4];
    const float* W2 = (const float*)d_in[5];
    const float* b2 = (const float*)d_in[6];
    const float* W3 = (const float*)d_in[7];
    const float* b3 = (const float*)d_in[8];
    const float* W4 = (const float*)d_in[9];
    const float* b4 = (const float*)d_in[10];
    const float* W5 = (const float*)d_in[11];
    const float* b5 = (const float*)d_in[12];

    const int grid = (BATCH / ROWS_PER_THREAD) / NTHREADS;  // 2048
    mlp_kernel<<<grid, NTHREADS>>>((const float4*)x, (float4*)d_out,
                                   W0, b0, W1, b1, W2, b2, W3, b3, W4, b4, W5, b5);
}

// round 9
// speedup vs baseline: 7.3406x; 7.3406x over previous
#include <cuda_runtime.h>

typedef unsigned long long u64;

// ---------------- packed f32x2 helpers (Blackwell FFMA2) ----------------
__device__ __forceinline__ u64 pack2(float a, float b) {
    u64 r; asm("mov.b64 %0, {%1, %2};" : "=l"(r) : "f"(a), "f"(b)); return r;
}
__device__ __forceinline__ u64 pack1(float a) { return pack2(a, a); }
__device__ __forceinline__ void unpack2(u64 v, float& a, float& b) {
    asm("mov.b64 {%0, %1}, %2;" : "=f"(a), "=f"(b) : "l"(v));
}
__device__ __forceinline__ u64 fma2(u64 a, u64 b, u64 c) {
    u64 d; asm("fma.rn.f32x2 %0, %1, %2, %3;" : "=l"(d) : "l"(a), "l"(b), "l"(c));
    return d;
}
__device__ __forceinline__ u64 relu2(u64 v) {
    float a, b; unpack2(v, a, b);
    a = fmaxf(a, 0.0f); b = fmaxf(b, 0.0f);
    return pack2(a, b);
}

// ---------------- constants ----------------
#define NTHREADS 128
#define ROWS_PER_THREAD 4
#define PAIRS 2
static constexpr int BATCH = 2097152;
static constexpr int CHUNK = BATCH / ROWS_PER_THREAD;  // 524288

// ---------------- shared weight table (u64 indices), raw, bias embedded --
// W0: 5 rows stride 10 [w0..w7, b, pad]    [0,50)
// W1..W4: 5 rows stride 6 [w0..w4, b]      [50,80) [80,110) [110,140) [140,170)
// W5: 4 rows stride 6 [w0..w4, b]          [170,194)
#define OFF_W0   0
#define OFF_W1   50
#define OFF_W2   80
#define OFF_W3   110
#define OFF_W4   140
#define OFF_W5   170
#define W_TOTAL  194

// raw table entry t: a single LDG from the right source (no arithmetic)
__device__ __forceinline__ float table_entry(
    int t,
    const float* __restrict__ W0, const float* __restrict__ b0,
    const float* __restrict__ W1, const float* __restrict__ b1,
    const float* __restrict__ W2, const float* __restrict__ b2,
    const float* __restrict__ W3, const float* __restrict__ b3,
    const float* __restrict__ W4, const float* __restrict__ b4,
    const float* __restrict__ W5, const float* __restrict__ b5) {
    if (t < 50) {
        int o = t / 10, k = t % 10;
        return (k < 8) ? W0[o * 8 + k] : ((k == 8) ? b0[o] : 0.0f);
    } else if (t < 80) {
        int i = t - OFF_W1, o = i / 6, k = i % 6;
        return (k < 5) ? W1[o * 5 + k] : b1[o];
    } else if (t < 110) {
        int i = t - OFF_W2, o = i / 6, k = i % 6;
        return (k < 5) ? W2[o * 5 + k] : b2[o];
    } else if (t < 140) {
        int i = t - OFF_W3, o = i / 6, k = i % 6;
        return (k < 5) ? W3[o * 5 + k] : b3[o];
    } else if (t < 170) {
        int i = t - OFF_W4, o = i / 6, k = i % 6;
        return (k < 5) ? W4[o * 5 + k] : b4[o];
    } else {
        int i = t - OFF_W5, o = i / 6, k = i % 6;
        return (k < 5) ? W5[o * 5 + k] : b5[o];
    }
}

// one 5->5 stage applied to both pairs; 3 LDS.128 per neuron row; optional relu
template <bool RELU>
__device__ __forceinline__ void stage5x5(u64 a[PAIRS][5], const u64* sw, int woff) {
    u64 h[PAIRS][5];
#pragma unroll
    for (int o = 0; o < 5; o++) {
        ulonglong2 wa = *reinterpret_cast<const ulonglong2*>(sw + woff + o * 6);
        ulonglong2 wb = *reinterpret_cast<const ulonglong2*>(sw + woff + o * 6 + 2);
        ulonglong2 wc = *reinterpret_cast<const ulonglong2*>(sw + woff + o * 6 + 4);
#pragma unroll
        for (int p = 0; p < PAIRS; p++) {
            u64 acc = wc.y;  // bias
            acc = fma2(a[p][0], wa.x, acc);
            acc = fma2(a[p][1], wa.y, acc);
            acc = fma2(a[p][2], wb.x, acc);
            acc = fma2(a[p][3], wb.y, acc);
            acc = fma2(a[p][4], wc.x, acc);
            h[p][o] = RELU ? relu2(acc) : acc;
        }
    }
#pragma unroll
    for (int p = 0; p < PAIRS; p++)
#pragma unroll
        for (int o = 0; o < 5; o++) a[p][o] = h[p][o];
}

__global__ __launch_bounds__(NTHREADS, 6) void mlp_kernel(
    const float4* __restrict__ x, float4* __restrict__ out,
    const float* __restrict__ W0, const float* __restrict__ b0,
    const float* __restrict__ W1, const float* __restrict__ b1,
    const float* __restrict__ W2, const float* __restrict__ b2,
    const float* __restrict__ W3, const float* __restrict__ b3,
    const float* __restrict__ W4, const float* __restrict__ b4,
    const float* __restrict__ W5, const float* __restrict__ b5) {
    __shared__ __align__(16) u64 sw[W_TOTAL];
    const int t = threadIdx.x;
    const int idx = blockIdx.x * NTHREADS + t;  // 0..CHUNK-1
    const float4* xp = x + 2u * (unsigned)idx;

    // front-batch all 8 input vectors (4 rows x 2 float4) — max MLP
    float4 xl[ROWS_PER_THREAD], xh[ROWS_PER_THREAD];
#pragma unroll
    for (int r = 0; r < ROWS_PER_THREAD; r++) {
        const float4* xr = xp + (size_t)r * (2 * CHUNK);
        xl[r] = __ldg(xr);
        xh[r] = __ldg(xr + 1);
    }

    // raw weight table: <=2 predicated LDG+STS per thread
    if (t < W_TOTAL)
        sw[t] = pack1(table_entry(t, W0, b0, W1, b1, W2, b2, W3, b3, W4, b4, W5, b5));
    {
        int t2 = t + NTHREADS;
        if (t2 < W_TOTAL)
            sw[t2] = pack1(table_entry(t2, W0, b0, W1, b1, W2, b2, W3, b3, W4, b4, W5, b5));
    }
    __syncthreads();

    // pack inputs into f32x2 lanes (row 2p paired with row 2p+1)
    u64 xv[PAIRS][8];
#pragma unroll
    for (int p = 0; p < PAIRS; p++) {
        const int ra = 2 * p, rb = 2 * p + 1;
        xv[p][0] = pack2(xl[ra].x, xl[rb].x); xv[p][1] = pack2(xl[ra].y, xl[rb].y);
        xv[p][2] = pack2(xl[ra].z, xl[rb].z); xv[p][3] = pack2(xl[ra].w, xl[rb].w);
        xv[p][4] = pack2(xh[ra].x, xh[rb].x); xv[p][5] = pack2(xh[ra].y, xh[rb].y);
        xv[p][6] = pack2(xh[ra].z, xh[rb].z); xv[p][7] = pack2(xh[ra].w, xh[rb].w);
    }

    // ---- layer0: 8 -> 5, NO relu ----
    u64 a[PAIRS][5];
#pragma unroll
    for (int o = 0; o < 5; o++) {
        ulonglong2 wa = *reinterpret_cast<const ulonglong2*>(sw + OFF_W0 + o * 10);
        ulonglong2 wb = *reinterpret_cast<const ulonglong2*>(sw + OFF_W0 + o * 10 + 2);
        ulonglong2 wc = *reinterpret_cast<const ulonglong2*>(sw + OFF_W0 + o * 10 + 4);
        ulonglong2 wd = *reinterpret_cast<const ulonglong2*>(sw + OFF_W0 + o * 10 + 6);
        ulonglong2 we = *reinterpret_cast<const ulonglong2*>(sw + OFF_W0 + o * 10 + 8);
#pragma unroll
        for (int p = 0; p < PAIRS; p++) {
            u64 acc = we.x;  // bias
            acc = fma2(xv[p][0], wa.x, acc);
            acc = fma2(xv[p][1], wa.y, acc);
            acc = fma2(xv[p][2], wb.x, acc);
            acc = fma2(xv[p][3], wb.y, acc);
            acc = fma2(xv[p][4], wc.x, acc);
            acc = fma2(xv[p][5], wc.y, acc);
            acc = fma2(xv[p][6], wd.x, acc);
            acc = fma2(xv[p][7], wd.y, acc);
            a[p][o] = acc;
        }
    }

    // ---- layers 1..4: 5 -> relu(5) ----
    stage5x5<true>(a, sw, OFF_W1);
    stage5x5<true>(a, sw, OFF_W2);
    stage5x5<true>(a, sw, OFF_W3);
    stage5x5<true>(a, sw, OFF_W4);

    // ---- layer5: 5 -> relu(4) + streaming store ----
    float res[ROWS_PER_THREAD][4];
#pragma unroll
    for (int o = 0; o < 4; o++) {
        ulonglong2 wa = *reinterpret_cast<const ulonglong2*>(sw + OFF_W5 + o * 6);
        ulonglong2 wb = *reinterpret_cast<const ulonglong2*>(sw + OFF_W5 + o * 6 + 2);
        ulonglong2 wc = *reinterpret_cast<const ulonglong2*>(sw + OFF_W5 + o * 6 + 4);
#pragma unroll
        for (int p = 0; p < PAIRS; p++) {
            u64 acc = wc.y;  // bias
            acc = fma2(a[p][0], wa.x, acc);
            acc = fma2(a[p][1], wa.y, acc);
            acc = fma2(a[p][2], wb.x, acc);
            acc = fma2(a[p][3], wb.y, acc);
            acc = fma2(a[p][4], wc.x, acc);
            acc = relu2(acc);
            unpack2(acc, res[2 * p][o], res[2 * p + 1][o]);
        }
    }
    float4* op = out + idx;
#pragma unroll
    for (int r = 0; r < ROWS_PER_THREAD; r++) {
        __stcs(op + (size_t)r * CHUNK,
               make_float4(res[r][0], res[r][1], res[r][2], res[r][3]));
    }
}

extern "C" void kernel_launch(void* const* d_in, const int* in_sizes, int n_in,
                              void* d_out, int out_size) {
    const float* x  = (const float*)d_in[0];
    const float* W0 = (const float*)d_in[1];
    const float* b0 = (const float*)d_in[2];
    const float* W1 = (const float*)d_in[3];
    const float* b1 = (const float*)d_in[4];
    const float* W2 = (const float*)d_in[5];
    const float* b2 = (const float*)d_in[6];
    const float* W3 = (const float*)d_in[7];
    const float* b3 = (const float*)d_in[8];
    const float* W4 = (const float*)d_in[9];
    const float* b4 = (const float*)d_in[10];
    const float* W5 = (const float*)d_in[11];
    const float* b5 = (const float*)d_in[12];

    const int grid = (BATCH / ROWS_PER_THREAD) / NTHREADS;  // 4096
    mlp_kernel<<<grid, NTHREADS>>>((const float4*)x, (float4*)d_out,
                                   W0, b0, W1, b1, W2, b2, W3, b3, W4, b4, W5, b5);
}

// round 10
// speedup vs baseline: 7.3499x; 1.0013x over previous
#include <cuda_runtime.h>

typedef unsigned long long u64;

// ---------------- packed f32x2 helpers (Blackwell FFMA2) ----------------
__device__ __forceinline__ u64 pack2(float a, float b) {
    u64 r; asm("mov.b64 %0, {%1, %2};" : "=l"(r) : "f"(a), "f"(b)); return r;
}
__device__ __forceinline__ u64 pack1(float a) { return pack2(a, a); }
__device__ __forceinline__ void unpack2(u64 v, float& a, float& b) {
    asm("mov.b64 {%0, %1}, %2;" : "=f"(a), "=f"(b) : "l"(v));
}
__device__ __forceinline__ u64 fma2(u64 a, u64 b, u64 c) {
    u64 d; asm("fma.rn.f32x2 %0, %1, %2, %3;" : "=l"(d) : "l"(a), "l"(b), "l"(c));
    return d;
}
__device__ __forceinline__ u64 relu2(u64 v) {
    float a, b; unpack2(v, a, b);
    a = fmaxf(a, 0.0f); b = fmaxf(b, 0.0f);
    return pack2(a, b);
}

// ---------------- constants ----------------
#define NTHREADS 128
#define ROWS_PER_THREAD 4
#define PAIRS 2
static constexpr int BATCH = 2097152;
static constexpr int CHUNK = BATCH / ROWS_PER_THREAD;  // 524288

// ---------------- shared weight table (u64 indices), raw, bias embedded --
// W0: 5 rows stride 10 [w0..w7, b, pad]    [0,50)
// W1..W4: 5 rows stride 6 [w0..w4, b]      [50,80) [80,110) [110,140) [140,170)
// W5: 4 rows stride 6 [w0..w4, b]          [170,194)
#define OFF_W0   0
#define OFF_W1   50
#define OFF_W2   80
#define OFF_W3   110
#define OFF_W4   140
#define OFF_W5   170
#define W_TOTAL  194

// raw table entry t: a single LDG from the right source (no arithmetic)
__device__ __forceinline__ float table_entry(
    int t,
    const float* __restrict__ W0, const float* __restrict__ b0,
    const float* __restrict__ W1, const float* __restrict__ b1,
    const float* __restrict__ W2, const float* __restrict__ b2,
    const float* __restrict__ W3, const float* __restrict__ b3,
    const float* __restrict__ W4, const float* __restrict__ b4,
    const float* __restrict__ W5, const float* __restrict__ b5) {
    if (t < 50) {
        int o = t / 10, k = t % 10;
        return (k < 8) ? W0[o * 8 + k] : ((k == 8) ? b0[o] : 0.0f);
    } else if (t < 80) {
        int i = t - OFF_W1, o = i / 6, k = i % 6;
        return (k < 5) ? W1[o * 5 + k] : b1[o];
    } else if (t < 110) {
        int i = t - OFF_W2, o = i / 6, k = i % 6;
        return (k < 5) ? W2[o * 5 + k] : b2[o];
    } else if (t < 140) {
        int i = t - OFF_W3, o = i / 6, k = i % 6;
        return (k < 5) ? W3[o * 5 + k] : b3[o];
    } else if (t < 170) {
        int i = t - OFF_W4, o = i / 6, k = i % 6;
        return (k < 5) ? W4[o * 5 + k] : b4[o];
    } else {
        int i = t - OFF_W5, o = i / 6, k = i % 6;
        return (k < 5) ? W5[o * 5 + k] : b5[o];
    }
}

// one 5->5 stage applied to both pairs; 3 LDS.128 per neuron row; optional relu
template <bool RELU>
__device__ __forceinline__ void stage5x5(u64 a[PAIRS][5], const u64* sw, int woff) {
    u64 h[PAIRS][5];
#pragma unroll
    for (int o = 0; o < 5; o++) {
        ulonglong2 wa = *reinterpret_cast<const ulonglong2*>(sw + woff + o * 6);
        ulonglong2 wb = *reinterpret_cast<const ulonglong2*>(sw + woff + o * 6 + 2);
        ulonglong2 wc = *reinterpret_cast<const ulonglong2*>(sw + woff + o * 6 + 4);
#pragma unroll
        for (int p = 0; p < PAIRS; p++) {
            u64 acc = wc.y;  // bias
            acc = fma2(a[p][0], wa.x, acc);
            acc = fma2(a[p][1], wa.y, acc);
            acc = fma2(a[p][2], wb.x, acc);
            acc = fma2(a[p][3], wb.y, acc);
            acc = fma2(a[p][4], wc.x, acc);
            h[p][o] = RELU ? relu2(acc) : acc;
        }
    }
#pragma unroll
    for (int p = 0; p < PAIRS; p++)
#pragma unroll
        for (int o = 0; o < 5; o++) a[p][o] = h[p][o];
}

__global__ __launch_bounds__(NTHREADS, 6) void mlp_kernel(
    const float4* __restrict__ x, float4* __restrict__ out,
    const float* __restrict__ W0, const float* __restrict__ b0,
    const float* __restrict__ W1, const float* __restrict__ b1,
    const float* __restrict__ W2, const float* __restrict__ b2,
    const float* __restrict__ W3, const float* __restrict__ b3,
    const float* __restrict__ W4, const float* __restrict__ b4,
    const float* __restrict__ W5, const float* __restrict__ b5) {
    __shared__ __align__(16) u64 sw[W_TOTAL];
    const int t = threadIdx.x;
    const int idx = blockIdx.x * NTHREADS + t;  // 0..CHUNK-1
    const float4* xp = x + 2u * (unsigned)idx;

    // front-batch all 8 input vectors (4 rows x 2 float4) — max MLP
    float4 xl[ROWS_PER_THREAD], xh[ROWS_PER_THREAD];
#pragma unroll
    for (int r = 0; r < ROWS_PER_THREAD; r++) {
        const float4* xr = xp + (size_t)r * (2 * CHUNK);
        xl[r] = __ldg(xr);
        xh[r] = __ldg(xr + 1);
    }

    // raw weight table: <=2 predicated LDG+STS per thread
    if (t < W_TOTAL)
        sw[t] = pack1(table_entry(t, W0, b0, W1, b1, W2, b2, W3, b3, W4, b4, W5, b5));
    {
        int t2 = t + NTHREADS;
        if (t2 < W_TOTAL)
            sw[t2] = pack1(table_entry(t2, W0, b0, W1, b1, W2, b2, W3, b3, W4, b4, W5, b5));
    }
    __syncthreads();

    // pack inputs into f32x2 lanes (row 2p paired with row 2p+1)
    u64 xv[PAIRS][8];
#pragma unroll
    for (int p = 0; p < PAIRS; p++) {
        const int ra = 2 * p, rb = 2 * p + 1;
        xv[p][0] = pack2(xl[ra].x, xl[rb].x); xv[p][1] = pack2(xl[ra].y, xl[rb].y);
        xv[p][2] = pack2(xl[ra].z, xl[rb].z); xv[p][3] = pack2(xl[ra].w, xl[rb].w);
        xv[p][4] = pack2(xh[ra].x, xh[rb].x); xv[p][5] = pack2(xh[ra].y, xh[rb].y);
        xv[p][6] = pack2(xh[ra].z, xh[rb].z); xv[p][7] = pack2(xh[ra].w, xh[rb].w);
    }

    // ---- layer0: 8 -> 5, NO relu ----
    u64 a[PAIRS][5];
#pragma unroll
    for (int o = 0; o < 5; o++) {
        ulonglong2 wa = *reinterpret_cast<const ulonglong2*>(sw + OFF_W0 + o * 10);
        ulonglong2 wb = *reinterpret_cast<const ulonglong2*>(sw + OFF_W0 + o * 10 + 2);
        ulonglong2 wc = *reinterpret_cast<const ulonglong2*>(sw + OFF_W0 + o * 10 + 4);
        ulonglong2 wd = *reinterpret_cast<const ulonglong2*>(sw + OFF_W0 + o * 10 + 6);
        ulonglong2 we = *reinterpret_cast<const ulonglong2*>(sw + OFF_W0 + o * 10 + 8);
#pragma unroll
        for (int p = 0; p < PAIRS; p++) {
            u64 acc = we.x;  // bias
            acc = fma2(xv[p][0], wa.x, acc);
            acc = fma2(xv[p][1], wa.y, acc);
            acc = fma2(xv[p][2], wb.x, acc);
            acc = fma2(xv[p][3], wb.y, acc);
            acc = fma2(xv[p][4], wc.x, acc);
            acc = fma2(xv[p][5], wc.y, acc);
            acc = fma2(xv[p][6], wd.x, acc);
            acc = fma2(xv[p][7], wd.y, acc);
            a[p][o] = acc;
        }
    }

    // ---- layers 1..4: 5 -> relu(5) ----
    stage5x5<true>(a, sw, OFF_W1);
    stage5x5<true>(a, sw, OFF_W2);
    stage5x5<true>(a, sw, OFF_W3);
    stage5x5<true>(a, sw, OFF_W4);

    // ---- layer5: 5 -> relu(4) + streaming store ----
    float res[ROWS_PER_THREAD][4];
#pragma unroll
    for (int o = 0; o < 4; o++) {
        ulonglong2 wa = *reinterpret_cast<const ulonglong2*>(sw + OFF_W5 + o * 6);
        ulonglong2 wb = *reinterpret_cast<const ulonglong2*>(sw + OFF_W5 + o * 6 + 2);
        ulonglong2 wc = *reinterpret_cast<const ulonglong2*>(sw + OFF_W5 + o * 6 + 4);
#pragma unroll
        for (int p = 0; p < PAIRS; p++) {
            u64 acc = wc.y;  // bias
            acc = fma2(a[p][0], wa.x, acc);
            acc = fma2(a[p][1], wa.y, acc);
            acc = fma2(a[p][2], wb.x, acc);
            acc = fma2(a[p][3], wb.y, acc);
            acc = fma2(a[p][4], wc.x, acc);
            acc = relu2(acc);
            unpack2(acc, res[2 * p][o], res[2 * p + 1][o]);
        }
    }
    float4* op = out + idx;
#pragma unroll
    for (int r = 0; r < ROWS_PER_THREAD; r++) {
        __stcs(op + (size_t)r * CHUNK,
               make_float4(res[r][0], res[r][1], res[r][2], res[r][3]));
    }
}

extern "C" void kernel_launch(void* const* d_in, const int* in_sizes, int n_in,
                              void* d_out, int out_size) {
    const float* x  = (const float*)d_in[0];
    const float* W0 = (const float*)d_in[1];
    const float* b0 = (const float*)d_in[2];
    const float* W1 = (const float*)d_in[3];
    const float* b1 = (const float*)d_in[4];
    const float* W2 = (const float*)d_in[5];
    const float* b2 = (const float*)d_in[6];
    const float* W3 = (const float*)d_in[7];
    const float* b3 = (const float*)d_in[8];
    const float* W4 = (const float*)d_in[9];
    const float* b4 = (const float*)d_in[10];
    const float* W5 = (const float*)d_in[11];
    const float* b5 = (const float*)d_in[12];

    const int grid = (BATCH / ROWS_PER_THREAD) / NTHREADS;  // 4096
    mlp_kernel<<<grid, NTHREADS>>>((const float4*)x, (float4*)d_out,
                                   W0, b0, W1, b1, W2, b2, W3, b3, W4, b4, W5, b5);
}